// round 5
// baseline (speedup 1.0000x reference)
#include <cuda_runtime.h>
#include <cuda_bf16.h>

#define R2C 0.70710678118654752f

// Fused: separable blur -> per-8x8-block T(X)=CXC-SXS -> nonlin -> T ->
// residual -> Haar soft-threshold refine. One thread owns a full 8x8 block:
// both transposes + Haar are register-local. CTA(128 thr) = 128x64 px region.

__device__ __forceinline__ float soft05(float x) {
    return copysignf(fmaxf(fabsf(x) - 0.05f, 0.0f), x);
}

// x[8] -> o[8] = {RE0,RE1,RE2,RE3,RE4,SI1,SI2,SI3}, unnormalized.
__device__ __forceinline__ void dft8_real(const float* x, float* o) {
    float s04 = x[0] + x[4], d04 = x[0] - x[4];
    float s26 = x[2] + x[6], d26 = x[2] - x[6];
    float s15 = x[1] + x[5], d15 = x[1] - x[5];
    float s37 = x[3] + x[7], d37 = x[3] - x[7];
    float t1 = s04 + s26, t2 = s15 + s37;
    o[0] = t1 + t2; o[4] = t1 - t2; o[2] = s04 - s26;
    float u = d15 - d37, v = d15 + d37;
    o[1] = fmaf(R2C, u, d04); o[3] = fmaf(-R2C, u, d04);
    o[5] = fmaf(R2C, v, d26);
    o[6] = s15 - s37;
    o[7] = fmaf(R2C, v, -d26);
}

// o[u] = cosDFT(q)[u] - sinDFT(w)[u], raw/unscaled.
__device__ __forceinline__ void dft8_combine(const float* q, const float* w, float* o) {
    float s04 = q[0] + q[4], d04 = q[0] - q[4];
    float s26 = q[2] + q[6];
    float s15 = q[1] + q[5], d15 = q[1] - q[5];
    float s37 = q[3] + q[7], d37 = q[3] - q[7];
    float t1 = s04 + s26, t2 = s15 + s37;
    float RE0 = t1 + t2, RE4 = t1 - t2, RE2 = s04 - s26;
    float uq = d15 - d37;
    float RE1 = fmaf(R2C, uq, d04), RE3 = fmaf(-R2C, uq, d04);
    float d26w = w[2] - w[6];
    float vw = (w[1] - w[5]) + (w[3] - w[7]);
    float SI1 = fmaf(R2C, vw, d26w);
    float SI2 = (w[1] + w[5]) - (w[3] + w[7]);
    float SI3 = fmaf(R2C, vw, -d26w);
    o[0] = RE0;        o[4] = RE4;
    o[1] = RE1 - SI1;  o[7] = RE1 + SI1;
    o[2] = RE2 - SI2;  o[6] = RE2 + SI2;
    o[3] = RE3 - SI3;  o[5] = RE3 + SI3;
}

__global__ __launch_bounds__(128) void sas_fused3_kernel(
    const float* __restrict__ in, float* __restrict__ out)
{
    // tile4[bcol][row 0..65][h 0..1]: hblurred, stride 133 f4 per bcol
    // (133 odd -> conflict-free strided vblur LDS.128 AND loader STS.128).
    __shared__ float4 tile4[16 * 133];

    const int t = threadIdx.x;
    const int warp = t >> 5;
    const int lane = t & 31;
    const int tileX = blockIdx.x * 128;
    const int tileY = blockIdx.y * 64;
    const int z = blockIdx.z;
    const float* img = in + (size_t)z * (512 * 512);

    const float e1 = expf(-0.78125f);          // exp(-1/(2*0.8^2))
    const float w0 = 1.0f / (1.0f + 2.0f * e1);
    const float w1 = e1 * w0;

    // ---- Loader: horizontal blur, global -> smem ----
    {
        const int lb = lane & 15;              // bcol
        const int lh = lane >> 4;              // half (cols lb*8 + lh*4 ..+3)
        const int G = 2 * lb + lh;             // 4-col group 0..31
        const int gl = G - 1, gr = G + 1;
        const int llane = ((gl >> 1) & 15) + ((gl & 1) << 4);
        const int rlane = ((gr >> 1) & 15) + ((gr & 1) << 4);
        const int gcol = tileX + 4 * G;
        for (int r = warp; r < 66; r += 4) {
            int gy = tileY + r - 1;
            gy = (gy < 0) ? -gy : ((gy > 511) ? 1022 - gy : gy);
            const float* row = img + (size_t)gy * 512;
            float4 A = *(const float4*)(row + gcol);
            float lv = __shfl_sync(0xffffffffu, A.w, llane);
            float rv = __shfl_sync(0xffffffffu, A.x, rlane);
            if (G == 0)  lv = (tileX == 0)      ? A.y : row[gcol - 1];
            if (G == 31) rv = (gcol + 4 > 511)  ? A.z : row[gcol + 4];
            float4 o;
            o.x = fmaf(w1, lv + A.y,  w0 * A.x);
            o.y = fmaf(w1, A.x + A.z, w0 * A.y);
            o.z = fmaf(w1, A.y + A.w, w0 * A.z);
            o.w = fmaf(w1, A.z + rv,  w0 * A.w);
            tile4[lb * 133 + r * 2 + lh] = o;
        }
    }
    __syncthreads();   // tile never overwritten -> only sync in kernel

    const int bcol = t & 15;
    const int brow = t >> 4;
    const float4* tb = &tile4[bcol * 133 + brow * 16];  // row rr at tb[rr*2+h]

    // ---- Vertical blur (rolling window) + row DFT -> tt ----
    float tt[8][8];
    {
        float4 A0 = tb[0], A1 = tb[1];
        float4 B0 = tb[2], B1 = tb[3];
        #pragma unroll
        for (int u = 0; u < 8; u++) {
            float4 C0 = tb[(u + 2) * 2], C1 = tb[(u + 2) * 2 + 1];
            float g[8];
            g[0] = fmaf(w1, A0.x + C0.x, w0 * B0.x);
            g[1] = fmaf(w1, A0.y + C0.y, w0 * B0.y);
            g[2] = fmaf(w1, A0.z + C0.z, w0 * B0.z);
            g[3] = fmaf(w1, A0.w + C0.w, w0 * B0.w);
            g[4] = fmaf(w1, A1.x + C1.x, w0 * B1.x);
            g[5] = fmaf(w1, A1.y + C1.y, w0 * B1.y);
            g[6] = fmaf(w1, A1.z + C1.z, w0 * B1.z);
            g[7] = fmaf(w1, A1.w + C1.w, w0 * B1.w);
            dft8_real(g, tt[u]);
            A0 = B0; A1 = B1; B0 = C0; B1 = C1;
        }
    }

    // ---- Forward column combine -> nonlin -> column DFT -> cc ----
    const int   jpt[8] = {0, 1, 2, 3, 4, 3, 2, 1};
    const int   ixt[8] = {5, 5, 6, 7, 5, 7, 6, 5};      // dummy 5 where sg=0
    const float sgt[8] = {0.f, 1.f, 1.f, 1.f, 0.f, -1.f, -1.f, -1.f};
    float cc[8][8];
    #pragma unroll
    for (int j = 0; j < 8; j++) {
        const int jp = jpt[j];
        const int ix = ixt[j];
        const float sg = sgt[j];
        float q[8], w[8];
        #pragma unroll
        for (int k = 0; k < 8; k++) { q[k] = tt[k][jp]; w[k] = sg * tt[k][ix]; }
        float cr[8], cf[8];
        dft8_combine(q, w, cr);
        #pragma unroll
        for (int u = 0; u < 8; u++) {
            float c = cr[u] * 0.125f;                   // fold ortho 1/8
            float m = fminf(fabsf(c) * 0.4f, 1.0f);     // shrink below 2.5
            c *= m;
            cf[u] = fminf(fmaxf(c, -10.0f), 10.0f);     // clip
        }
        dft8_real(cf, cc[j]);
    }

    // ---- Inverse rows + residual (recompute g) + Haar + store ----
    const int bidx = z / 3;
    const int cch = z - bidx * 3;
    float* outI = out + ((size_t)(bidx * 6 + cch) * 512 + tileY + brow * 8) * 512
                      + tileX + bcol * 8;
    float* outR = outI + (size_t)3 * 512 * 512;

    float4 A0 = tb[0], A1 = tb[1];
    float4 B0 = tb[2], B1 = tb[3];
    #pragma unroll
    for (int p = 0; p < 4; p++) {
        float4 C0 = tb[(2 * p + 2) * 2], C1 = tb[(2 * p + 2) * 2 + 1];
        float4 D0 = tb[(2 * p + 3) * 2], D1 = tb[(2 * p + 3) * 2 + 1];

        float g0[8], g1[8];
        g0[0] = fmaf(w1, A0.x + C0.x, w0 * B0.x);
        g0[1] = fmaf(w1, A0.y + C0.y, w0 * B0.y);
        g0[2] = fmaf(w1, A0.z + C0.z, w0 * B0.z);
        g0[3] = fmaf(w1, A0.w + C0.w, w0 * B0.w);
        g0[4] = fmaf(w1, A1.x + C1.x, w0 * B1.x);
        g0[5] = fmaf(w1, A1.y + C1.y, w0 * B1.y);
        g0[6] = fmaf(w1, A1.z + C1.z, w0 * B1.z);
        g0[7] = fmaf(w1, A1.w + C1.w, w0 * B1.w);
        g1[0] = fmaf(w1, B0.x + D0.x, w0 * C0.x);
        g1[1] = fmaf(w1, B0.y + D0.y, w0 * C0.y);
        g1[2] = fmaf(w1, B0.z + D0.z, w0 * C0.z);
        g1[3] = fmaf(w1, B0.w + D0.w, w0 * C0.w);
        g1[4] = fmaf(w1, B1.x + D1.x, w0 * C1.x);
        g1[5] = fmaf(w1, B1.y + D1.y, w0 * C1.y);
        g1[6] = fmaf(w1, B1.z + D1.z, w0 * C1.z);
        g1[7] = fmaf(w1, B1.w + D1.w, w0 * C1.w);

        float id0[8], id1[8];
        {
            const int u = 2 * p;
            const int up = jpt[u], ux = ixt[u];
            const float sg = sgt[u];
            float q[8], w[8], raw[8];
            #pragma unroll
            for (int j = 0; j < 8; j++) { q[j] = cc[j][up]; w[j] = sg * cc[j][ux]; }
            dft8_combine(q, w, raw);
            #pragma unroll
            for (int x = 0; x < 8; x++) id0[x] = raw[x] * 0.125f;
        }
        {
            const int u = 2 * p + 1;
            const int up = jpt[u], ux = ixt[u];
            const float sg = sgt[u];
            float q[8], w[8], raw[8];
            #pragma unroll
            for (int j = 0; j < 8; j++) { q[j] = cc[j][up]; w[j] = sg * cc[j][ux]; }
            dft8_combine(q, w, raw);
            #pragma unroll
            for (int x = 0; x < 8; x++) id1[x] = raw[x] * 0.125f;
        }

        float oI0[8], oI1[8], oR0[8], oR1[8];
        #pragma unroll
        for (int m = 0; m < 4; m++) {
            {   // I-branch
                float a = id0[2*m], b = id0[2*m+1], c = id1[2*m], d = id1[2*m+1];
                float LL = (a + b + c + d) * 0.5f;
                float LH = soft05((a + b - c - d) * 0.5f);
                float HL = soft05((a - b + c - d) * 0.5f);
                float HH = soft05((a - b - c + d) * 0.5f);
                oI0[2*m]   = 0.5f * (LL + LH + HL + HH);
                oI0[2*m+1] = 0.5f * (LL + LH - HL - HH);
                oI1[2*m]   = 0.5f * (LL - LH + HL - HH);
                oI1[2*m+1] = 0.5f * (LL - LH - HL + HH);
            }
            {   // R-branch
                float a = g0[2*m]   - id0[2*m];
                float b = g0[2*m+1] - id0[2*m+1];
                float c = g1[2*m]   - id1[2*m];
                float d = g1[2*m+1] - id1[2*m+1];
                float LL = (a + b + c + d) * 0.5f;
                float LH = soft05((a + b - c - d) * 0.5f);
                float HL = soft05((a - b + c - d) * 0.5f);
                float HH = soft05((a - b - c + d) * 0.5f);
                oR0[2*m]   = 0.5f * (LL + LH + HL + HH);
                oR0[2*m+1] = 0.5f * (LL + LH - HL - HH);
                oR1[2*m]   = 0.5f * (LL - LH + HL - HH);
                oR1[2*m+1] = 0.5f * (LL - LH - HL + HH);
            }
        }

        float* oI = outI + (size_t)(2 * p) * 512;
        float* oR = outR + (size_t)(2 * p) * 512;
        ((float4*)oI)[0]         = make_float4(oI0[0], oI0[1], oI0[2], oI0[3]);
        ((float4*)oI)[1]         = make_float4(oI0[4], oI0[5], oI0[6], oI0[7]);
        ((float4*)(oI + 512))[0] = make_float4(oI1[0], oI1[1], oI1[2], oI1[3]);
        ((float4*)(oI + 512))[1] = make_float4(oI1[4], oI1[5], oI1[6], oI1[7]);
        ((float4*)oR)[0]         = make_float4(oR0[0], oR0[1], oR0[2], oR0[3]);
        ((float4*)oR)[1]         = make_float4(oR0[4], oR0[5], oR0[6], oR0[7]);
        ((float4*)(oR + 512))[0] = make_float4(oR1[0], oR1[1], oR1[2], oR1[3]);
        ((float4*)(oR + 512))[1] = make_float4(oR1[4], oR1[5], oR1[6], oR1[7]);

        A0 = C0; A1 = C1; B0 = D0; B1 = D1;
    }
}

extern "C" void kernel_launch(void* const* d_in, const int* in_sizes, int n_in,
                              void* d_out, int out_size) {
    const float* I = (const float*)d_in[0];
    float* out = (float*)d_out;
    dim3 block(128);
    dim3 grid(512 / 128, 512 / 64, 96);   // 4 x 8 x 96 = 3072 CTAs
    sas_fused3_kernel<<<grid, block>>>(I, out);
}

// round 6
// speedup vs baseline: 1.4940x; 1.4940x over previous
#include <cuda_runtime.h>
#include <cuda_bf16.h>

#define R2C 0.70710678118654752f

__device__ __forceinline__ float soft05(float x) {
    return copysignf(fmaxf(fabsf(x) - 0.05f, 0.0f), x);
}

// x[8] -> o[8] = {RE0,RE1,RE2,RE3,RE4,SI1,SI2,SI3}, unnormalized.
__device__ __forceinline__ void dft8_real(const float* x, float* o) {
    float s04 = x[0] + x[4], d04 = x[0] - x[4];
    float s26 = x[2] + x[6], d26 = x[2] - x[6];
    float s15 = x[1] + x[5], d15 = x[1] - x[5];
    float s37 = x[3] + x[7], d37 = x[3] - x[7];
    float t1 = s04 + s26, t2 = s15 + s37;
    o[0] = t1 + t2; o[4] = t1 - t2; o[2] = s04 - s26;
    float u = d15 - d37, v = d15 + d37;
    o[1] = fmaf(R2C, u, d04); o[3] = fmaf(-R2C, u, d04);
    o[5] = fmaf(R2C, v, d26);
    o[6] = s15 - s37;
    o[7] = fmaf(R2C, v, -d26);
}

// o[u] = cosDFT_u(q) - sinDFT_u(w), raw/unscaled.
__device__ __forceinline__ void dft8_combine(const float* q, const float* w, float* o) {
    float s04 = q[0] + q[4], d04 = q[0] - q[4];
    float s26 = q[2] + q[6];
    float s15 = q[1] + q[5], d15 = q[1] - q[5];
    float s37 = q[3] + q[7], d37 = q[3] - q[7];
    float t1 = s04 + s26, t2 = s15 + s37;
    float RE0 = t1 + t2, RE4 = t1 - t2, RE2 = s04 - s26;
    float uq = d15 - d37;
    float RE1 = fmaf(R2C, uq, d04), RE3 = fmaf(-R2C, uq, d04);
    float d26w = w[2] - w[6];
    float vw = (w[1] - w[5]) + (w[3] - w[7]);
    float SI1 = fmaf(R2C, vw, d26w);
    float SI2 = (w[1] + w[5]) - (w[3] + w[7]);
    float SI3 = fmaf(R2C, vw, -d26w);
    o[0] = RE0;        o[4] = RE4;
    o[1] = RE1 - SI1;  o[7] = RE1 + SI1;
    o[2] = RE2 - SI2;  o[6] = RE2 + SI2;
    o[3] = RE3 - SI3;  o[5] = RE3 + SI3;
}

// o[u] = cosDFT_u(q) only (for columns with zero sine part).
__device__ __forceinline__ void dft8_cos(const float* q, float* o) {
    float s04 = q[0] + q[4], d04 = q[0] - q[4];
    float s26 = q[2] + q[6];
    float s15 = q[1] + q[5], d15 = q[1] - q[5];
    float s37 = q[3] + q[7], d37 = q[3] - q[7];
    float t1 = s04 + s26, t2 = s15 + s37;
    o[0] = t1 + t2; o[4] = t1 - t2;
    o[2] = s04 - s26; o[6] = o[2];
    float uq = d15 - d37;
    o[1] = fmaf(R2C, uq, d04); o[3] = fmaf(-R2C, uq, d04);
    o[5] = o[3]; o[7] = o[1];
}

// Combine for line pair (C0, C0+1). bb = 8 compressed lines of one block,
// line k at bb[k*8 .. k*8+7] = {RE0..RE4, SI1..SI3}.
template<int C0>
__device__ __forceinline__ void combine_pair(const float* __restrict__ bb,
                                             float* oA, float* oB) {
    constexpr int JP[8]  = {0, 1, 2, 3, 4, 3, 2, 1};
    constexpr int IXt[8] = {0, 5, 6, 7, 0, 7, 6, 5};
    constexpr float SGt[8] = {0.f, 1.f, 1.f, 1.f, 0.f, -1.f, -1.f, -1.f};

    float q[8];
    #pragma unroll
    for (int k = 0; k < 8; k++) q[k] = bb[k * 8 + JP[C0]];
    if constexpr (SGt[C0] == 0.f) {
        dft8_cos(q, oA);
    } else {
        float w[8];
        #pragma unroll
        for (int k = 0; k < 8; k++) w[k] = SGt[C0] * bb[k * 8 + IXt[C0]];
        dft8_combine(q, w, oA);
    }
    float q2[8], w2[8];
    #pragma unroll
    for (int k = 0; k < 8; k++) {
        q2[k] = bb[k * 8 + JP[C0 + 1]];
        w2[k] = SGt[C0 + 1] * bb[k * 8 + IXt[C0 + 1]];
    }
    dft8_combine(q2, w2, oB);
}

// Haar refine for a row pair (fully thread-local).
__device__ __forceinline__ void haar_pair(const float* e, const float* o,
                                          float* re, float* ro) {
    #pragma unroll
    for (int m = 0; m < 4; m++) {
        float a = e[2*m], b = e[2*m+1], c = o[2*m], d = o[2*m+1];
        float u0 = a + b, v0 = a - b, u1 = c + d, v1 = c - d;
        float LL = (u0 + u1) * 0.5f;
        float LH = soft05((u0 - u1) * 0.5f);
        float HL = soft05((v0 + v1) * 0.5f);
        float HH = soft05((v0 - v1) * 0.5f);
        float p  = LL + LH, qd = HL + HH;
        float rr = LL - LH, sd = HL - HH;
        re[2*m]   = 0.5f * (p + qd);
        re[2*m+1] = 0.5f * (p - qd);
        ro[2*m]   = 0.5f * (rr + sd);
        ro[2*m+1] = 0.5f * (rr - sd);
    }
}

__device__ __forceinline__ void nonlin8(float* c) {
    #pragma unroll
    for (int i = 0; i < 8; i++) {
        float v = c[i] * 0.125f;                 // fold ortho 1/8
        float m = fminf(fabsf(v) * 0.4f, 1.0f);  // shrink below 2.5
        v *= m;
        c[i] = fminf(fmaxf(v, -10.0f), 10.0f);   // clip
    }
}

// CTA = 64x64 px, 256 threads. Thread: blk = t&63 (bcol=blk&7, brow=blk>>3),
// r2 = t>>6 (warp-uniform) -> owns block rows 2*r2, 2*r2+1.
__global__ __launch_bounds__(256, 3) void sas_fused4_kernel(
    const float* __restrict__ in, float* __restrict__ out)
{
    // smemA: hblur panels (8 bcols x 66 rows x 8 cols, stride 540 -> read-
    // conflict-free); later reused as buf2 (64 blocks x 64, stride 68).
    __shared__ __align__(16) float smemA[4352];
    __shared__ __align__(16) float bufF[64 * 68];

    const int t = threadIdx.x;
    const int r2 = t >> 6;
    const int blk = t & 63;
    const int bcol = blk & 7;
    const int brow = blk >> 3;
    const int tileX = blockIdx.x * 64;
    const int tileY = blockIdx.y * 64;
    const int z = blockIdx.z;
    const float* img = in + (size_t)z * (512 * 512);

    const float e1 = expf(-0.78125f);            // exp(-1/(2*0.8^2))
    const float w0 = 1.0f / (1.0f + 2.0f * e1);
    const float w1 = e1 * w0;

    // ---- Loader: horizontal blur, global -> smem panels ----
    for (int s = t; s < 1056; s += 256) {        // 66 rows x 16 f4
        int row = s >> 4, f4c = s & 15;
        int gy = tileY + row - 1;
        gy = (gy < 0) ? -gy : ((gy > 511) ? 1022 - gy : gy);
        const float* rp = img + (size_t)gy * 512;
        int base = tileX + f4c * 4;
        float4 A = *(const float4*)(rp + base);
        float lv = (base == 0)   ? A.y : rp[base - 1];
        float rv = (base == 508) ? A.z : rp[base + 4];
        float4 o;
        o.x = fmaf(w1, lv  + A.y, w0 * A.x);
        o.y = fmaf(w1, A.x + A.z, w0 * A.y);
        o.z = fmaf(w1, A.y + A.w, w0 * A.z);
        o.w = fmaf(w1, A.z + rv,  w0 * A.w);
        *(float4*)(smemA + (f4c >> 1) * 540 + row * 8 + (f4c & 1) * 4) = o;
    }
    __syncthreads();

    // ---- Vertical blur (2 rows) + row DFT -> bufF ----
    const int R0 = brow * 8 + 2 * r2;            // strip-local row (and hb base)
    float g0[8], g1[8];
    {
        const float4* hp = (const float4*)(smemA + bcol * 540 + R0 * 8);
        float4 a0 = hp[0], a1 = hp[1];
        float4 b0 = hp[2], b1 = hp[3];
        float4 c0 = hp[4], c1 = hp[5];
        float4 d0 = hp[6], d1 = hp[7];
        g0[0] = fmaf(w1, a0.x + c0.x, w0 * b0.x);
        g0[1] = fmaf(w1, a0.y + c0.y, w0 * b0.y);
        g0[2] = fmaf(w1, a0.z + c0.z, w0 * b0.z);
        g0[3] = fmaf(w1, a0.w + c0.w, w0 * b0.w);
        g0[4] = fmaf(w1, a1.x + c1.x, w0 * b1.x);
        g0[5] = fmaf(w1, a1.y + c1.y, w0 * b1.y);
        g0[6] = fmaf(w1, a1.z + c1.z, w0 * b1.z);
        g0[7] = fmaf(w1, a1.w + c1.w, w0 * b1.w);
        g1[0] = fmaf(w1, b0.x + d0.x, w0 * c0.x);
        g1[1] = fmaf(w1, b0.y + d0.y, w0 * c0.y);
        g1[2] = fmaf(w1, b0.z + d0.z, w0 * c0.z);
        g1[3] = fmaf(w1, b0.w + d0.w, w0 * c0.w);
        g1[4] = fmaf(w1, b1.x + d1.x, w0 * c1.x);
        g1[5] = fmaf(w1, b1.y + d1.y, w0 * c1.y);
        g1[6] = fmaf(w1, b1.z + d1.z, w0 * c1.z);
        g1[7] = fmaf(w1, b1.w + d1.w, w0 * c1.w);
    }
    float* fb = bufF + blk * 68;
    {
        float ta[8], tb[8];
        dft8_real(g0, ta);
        dft8_real(g1, tb);
        float4* p0 = (float4*)(fb + 2 * r2 * 8);
        p0[0] = make_float4(ta[0], ta[1], ta[2], ta[3]);
        p0[1] = make_float4(ta[4], ta[5], ta[6], ta[7]);
        float4* p1 = (float4*)(fb + (2 * r2 + 1) * 8);
        p1[0] = make_float4(tb[0], tb[1], tb[2], tb[3]);
        p1[1] = make_float4(tb[4], tb[5], tb[6], tb[7]);
    }
    __syncthreads();

    // ---- Forward column combine (cols 2r2, 2r2+1) -> nonlin -> col DFT ----
    float cA[8], cB[8];
    switch (r2) {
        case 0: combine_pair<0>(fb, cA, cB); break;
        case 1: combine_pair<2>(fb, cA, cB); break;
        case 2: combine_pair<4>(fb, cA, cB); break;
        default: combine_pair<6>(fb, cA, cB); break;
    }
    nonlin8(cA);
    nonlin8(cB);
    float* b2 = smemA + blk * 68;                // reuse hblur storage
    {
        float sA[8], sB[8];
        dft8_real(cA, sA);
        dft8_real(cB, sB);
        float4* p0 = (float4*)(b2 + 2 * r2 * 8);
        p0[0] = make_float4(sA[0], sA[1], sA[2], sA[3]);
        p0[1] = make_float4(sA[4], sA[5], sA[6], sA[7]);
        float4* p1 = (float4*)(b2 + (2 * r2 + 1) * 8);
        p1[0] = make_float4(sB[0], sB[1], sB[2], sB[3]);
        p1[1] = make_float4(sB[4], sB[5], sB[6], sB[7]);
    }
    __syncthreads();

    // ---- Inverse row combine (rows 2r2, 2r2+1) ----
    float idA[8], idB[8];
    switch (r2) {
        case 0: combine_pair<0>(b2, idA, idB); break;
        case 1: combine_pair<2>(b2, idA, idB); break;
        case 2: combine_pair<4>(b2, idA, idB); break;
        default: combine_pair<6>(b2, idA, idB); break;
    }
    float rdA[8], rdB[8];
    #pragma unroll
    for (int x = 0; x < 8; x++) {
        idA[x] *= 0.125f;
        idB[x] *= 0.125f;
        rdA[x] = g0[x] - idA[x];
        rdB[x] = g1[x] - idB[x];
    }

    // ---- Haar refine (thread-local) + stores ----
    const int bidx = z / 3;
    const int cch = z - bidx * 3;
    const size_t obase =
        ((size_t)(bidx * 6 + cch) * 512 + (tileY + R0)) * 512 + tileX + bcol * 8;

    {
        float oa[8], ob[8];
        haar_pair(idA, idB, oa, ob);
        float4* p0 = (float4*)(out + obase);
        p0[0] = make_float4(oa[0], oa[1], oa[2], oa[3]);
        p0[1] = make_float4(oa[4], oa[5], oa[6], oa[7]);
        float4* p1 = (float4*)(out + obase + 512);
        p1[0] = make_float4(ob[0], ob[1], ob[2], ob[3]);
        p1[1] = make_float4(ob[4], ob[5], ob[6], ob[7]);
    }
    {
        float oa[8], ob[8];
        haar_pair(rdA, rdB, oa, ob);
        const size_t rbase = obase + (size_t)3 * 512 * 512;
        float4* p0 = (float4*)(out + rbase);
        p0[0] = make_float4(oa[0], oa[1], oa[2], oa[3]);
        p0[1] = make_float4(oa[4], oa[5], oa[6], oa[7]);
        float4* p1 = (float4*)(out + rbase + 512);
        p1[0] = make_float4(ob[0], ob[1], ob[2], ob[3]);
        p1[1] = make_float4(ob[4], ob[5], ob[6], ob[7]);
    }
}

extern "C" void kernel_launch(void* const* d_in, const int* in_sizes, int n_in,
                              void* d_out, int out_size) {
    const float* I = (const float*)d_in[0];
    float* out = (float*)d_out;
    dim3 block(256);
    dim3 grid(8, 8, 96);
    sas_fused4_kernel<<<grid, block>>>(I, out);
}